// round 13
// baseline (speedup 1.0000x reference)
#include <cuda_runtime.h>
#include <cuda_bf16.h>
#include <cstdint>
#include <math.h>

// ---------------- Problem constants ----------------
#define BB    64
#define CIN   128
#define COUT  256
#define LL    1024
#define MROWS (BB*LL)          // 65536

// ---------------- Scratch (device globals; no allocations allowed) ----------------
__device__ float d_xT[BB*LL*CIN];          // x transposed: [b,l,i]
__device__ float d_h1t[BB*LL*COUT];        // conv1 output  [b,l,o]
__device__ float d_xzrh[BB*LL*768];        // xz|xr|xh      [b,l,768]
__device__ float d_g[BB*LL*COUT];          // gated GRU out [b,l,j]
__device__ float d_w1t[384*COUT];          // conv1 weights [tap*128+i][o]
__device__ float d_wzrh[COUT*768];         // [c][gate*256+o]
__device__ float d_w2t[768*COUT];          // conv2 weights [tap*256+j][o]
__device__ float d_swt[CIN*COUT];          // skip weights  [i][o]

// ---------------- Fast transcendentals ----------------
__device__ __forceinline__ float fexp2a(float x) {
    float y; asm("ex2.approx.f32 %0, %1;" : "=f"(y) : "f"(x)); return y;
}
__device__ __forceinline__ float frcpa(float x) {
    float y; asm("rcp.approx.f32 %0, %1;" : "=f"(y) : "f"(x)); return y;
}
__device__ __forceinline__ float fsig(float x) {        // 1/(1+e^-x)
    return frcpa(1.0f + fexp2a(-1.4426950408889634f * x));
}
__device__ __forceinline__ float ftanh(float x) {       // 2*sig(2x)-1
    return fmaf(2.0f, frcpa(1.0f + fexp2a(-2.8853900817779268f * x)), -1.0f);
}

// ---------------- Prep: weight transposes ----------------
__global__ void prep_kernel(const float* __restrict__ conv1_w,
                            const float* __restrict__ Wz, const float* __restrict__ Wr,
                            const float* __restrict__ Wh,
                            const float* __restrict__ conv2_w,
                            const float* __restrict__ skip_w)
{
    int idx = blockIdx.x * blockDim.x + threadIdx.x;
    int n = gridDim.x * blockDim.x;
    for (int t = idx; t < 384*COUT; t += n) {
        int c = t >> 8, o = t & 255;
        int tap = c / CIN, i = c % CIN;
        d_w1t[t] = conv1_w[(o*CIN + i)*3 + tap];
    }
    for (int t = idx; t < COUT*768; t += n) {
        int c = t / 768, col = t % 768;
        int gate = col >> 8, o = col & 255;
        const float* W = (gate == 0) ? Wz : (gate == 1) ? Wr : Wh;
        d_wzrh[t] = W[o*COUT + c];
    }
    for (int t = idx; t < 768*COUT; t += n) {
        int c = t >> 8, o = t & 255;
        int tap = c >> 8, j = c & 255;
        d_w2t[t] = conv2_w[(o*COUT + j)*3 + tap];
    }
    for (int t = idx; t < CIN*COUT; t += n) {
        int c = t >> 8, o = t & 255;
        d_swt[t] = skip_w[o*CIN + c];
    }
}

// ---------------- Transpose x: [B,CIN,L] -> xT [B,L,CIN] ----------------
__global__ void transpose_x_kernel(const float* __restrict__ x)
{
    __shared__ float tile[32][33];
    int b = blockIdx.z;
    int l0 = blockIdx.x * 32;
    int i0 = blockIdx.y * 32;
    int tx = threadIdx.x, ty = threadIdx.y;
    for (int r = ty; r < 32; r += 8)
        tile[r][tx] = x[(b*CIN + i0 + r)*LL + l0 + tx];
    __syncthreads();
    for (int r = ty; r < 32; r += 8)
        d_xT[(b*LL + l0 + r)*CIN + i0 + tx] = tile[tx][r];
}

// ---------------- Tiled fp32 GEMM (128x128x8, 256 threads, 8x8/thread, dbl-buf) --
template<int MODE>
__global__ __launch_bounds__(256) void gemm_kernel(const float* __restrict__ b0p,
                                                   const float* __restrict__ b1p,
                                                   const float* __restrict__ b2p,
                                                   float* __restrict__ outp)
{
    constexpr int K = (MODE == 1) ? 384 : (MODE == 0) ? 256 : (MODE == 2) ? 768 : 128;
    constexpr int N = (MODE == 0) ? 768 : 256;
    constexpr int NIT = K / 8;

    __shared__ float As[2][8][128];
    __shared__ float Bs[2][8][128];

    int tid = threadIdx.x;
    int R0 = blockIdx.y * 128;
    int n0 = blockIdx.x * 128;
    int b = R0 >> 10;
    int l0 = R0 & 1023;

    const float* Bmat = (MODE == 1) ? d_w1t : (MODE == 0) ? d_wzrh
                       : (MODE == 2) ? d_w2t : d_swt;

    int ar = tid >> 1, ac = (tid & 1) << 2;
    int br = tid >> 5, bc = (tid & 31) << 2;
    int tm4 = (tid >> 4) << 2;
    int tn4 = (tid & 15) << 2;

    float acc[8][8];
#pragma unroll
    for (int i = 0; i < 8; i++)
#pragma unroll
        for (int j = 0; j < 8; j++) acc[i][j] = 0.0f;

    auto loadA = [&](int k0) -> float4 {
        int c = k0 + ac;
        if (MODE == 0) {
            return *(const float4*)&d_h1t[(R0 + ar)*COUT + c];
        } else if (MODE == 3) {
            return *(const float4*)&d_xT[(R0 + ar)*CIN + c];
        } else if (MODE == 1) {
            int tap = c >> 7, i = c & 127;
            int lp = l0 + ar - 4 + 2*tap;
            return (lp >= 0) ? *(const float4*)&d_xT[(b*LL + lp)*CIN + i]
                             : make_float4(0.f, 0.f, 0.f, 0.f);
        } else { // MODE == 2
            int tap = c >> 8, j = c & 255;
            int lp = l0 + ar - 4 + 2*tap;
            return (lp >= 0) ? *(const float4*)&d_g[(b*LL + lp)*COUT + j]
                             : make_float4(0.f, 0.f, 0.f, 0.f);
        }
    };
    auto loadB = [&](int k0) -> float4 {
        return *(const float4*)&Bmat[(k0 + br)*N + n0 + bc];
    };

    {
        float4 av = loadA(0), bv = loadB(0);
        As[0][ac + 0][ar] = av.x; As[0][ac + 1][ar] = av.y;
        As[0][ac + 2][ar] = av.z; As[0][ac + 3][ar] = av.w;
        *(float4*)&Bs[0][br][bc] = bv;
    }
    __syncthreads();

    for (int it = 0; it < NIT; it++) {
        int buf = it & 1;
        float4 nav, nbv;
        bool have = (it + 1 < NIT);
        if (have) { nav = loadA((it + 1) * 8); nbv = loadB((it + 1) * 8); }

#pragma unroll
        for (int kk = 0; kk < 8; kk++) {
            float4 a0 = *(const float4*)&As[buf][kk][tm4];
            float4 a1 = *(const float4*)&As[buf][kk][64 + tm4];
            float4 c0 = *(const float4*)&Bs[buf][kk][tn4];
            float4 c1 = *(const float4*)&Bs[buf][kk][64 + tn4];
            float am[8] = {a0.x, a0.y, a0.z, a0.w, a1.x, a1.y, a1.z, a1.w};
            float bn[8] = {c0.x, c0.y, c0.z, c0.w, c1.x, c1.y, c1.z, c1.w};
#pragma unroll
            for (int i = 0; i < 8; i++)
#pragma unroll
                for (int j = 0; j < 8; j++) acc[i][j] += am[i] * bn[j];
        }

        if (have) {
            int nb = buf ^ 1;
            As[nb][ac + 0][ar] = nav.x; As[nb][ac + 1][ar] = nav.y;
            As[nb][ac + 2][ar] = nav.z; As[nb][ac + 3][ar] = nav.w;
            *(float4*)&Bs[nb][br][bc] = nbv;
        }
        __syncthreads();
    }

#pragma unroll
    for (int i = 0; i < 8; i++) {
        int rr = (i < 4) ? (tm4 + i) : (64 + tm4 + i - 4);
        int R = R0 + rr;
        int l = R & 1023;
#pragma unroll
        for (int j = 0; j < 8; j++) {
            int cc = (j < 4) ? (tn4 + j) : (64 + tn4 + j - 4);
            int nn = n0 + cc;
            float v = acc[i][j];
            if (MODE == 0) {
                float bias = (nn < 256) ? b0p[nn] : (nn < 512) ? b1p[nn - 256] : b2p[nn - 512];
                d_xzrh[R*768 + nn] = v + bias;
            } else if (MODE == 1) {
                v += b0p[nn];
                d_h1t[R*COUT + nn] = (v > 0.f) ? v : 0.2f * v;
            } else if (MODE == 2) {
                v += b0p[nn];
                v = (v > 0.f) ? v : 0.2f * v;
                outp[((size_t)b << 18) + ((size_t)nn << 10) + l] = v;
            } else { // MODE 3
                outp[((size_t)b << 18) + ((size_t)nn << 10) + l] += v + b0p[nn];
            }
        }
    }
}

// ---------------- Cluster-based GRU scan (8-way k-split / 4-way j-split) --------
// 32 clusters x 4 CTAs, 2 batches per cluster. CTA rank r owns j-slice
// [r*64, r*64+64) with its 192 KB U slice stationary in SMEM. Lane layout:
// jsub = lane>>3 picks a 2-row j subgroup, ksub = lane&7 picks a strided 8-way
// k-partition (chunks c == ksub mod 8). Butterfly reduction is only 3 levels
// over the 8 ksub lanes (36 shuffles vs 240 before); gate math runs straight
// from registers on lanes ksub<4 with approx sigmoid/tanh.
__global__ __launch_bounds__(256, 1) __cluster_dims__(4, 1, 1)
void scan_kernel(const float* __restrict__ Uz, const float* __restrict__ Ur,
                 const float* __restrict__ Uh,
                 const float* __restrict__ Uzb, const float* __restrict__ Urb,
                 const float* __restrict__ Uhb, const float* __restrict__ aw)
{
    extern __shared__ float sm[];
    float* Usm   = sm;             // [3][64][256] = 49152 floats (192 KB)
    float* hsm   = sm + 49152;     // [2 parities][2 batches][256]
    float* bsm   = sm + 50176;     // [3][64]

    int tid  = threadIdx.x;
    int rank = blockIdx.x & 3;
    int cid  = blockIdx.x >> 2;
    int b0 = cid * 2;
    int j0 = rank * 64;

    // Stationary U slice: Usm[g][jl][k] = Ug[(j0+jl)*256 + k]
    for (int t = tid; t < 64*256; t += 256) {
        Usm[t]         = Uz[j0*COUT + t];
        Usm[16384 + t] = Ur[j0*COUT + t];
        Usm[32768 + t] = Uh[j0*COUT + t];
    }
    if (tid < 64) {
        bsm[tid]       = Uzb[j0 + tid];
        bsm[64 + tid]  = Urb[j0 + tid];
        bsm[128 + tid] = Uhb[j0 + tid];
    }
    for (int t = tid; t < 1024; t += 256) hsm[t] = 0.f;  // h0 = 0, both parities
    float cthr = 0.1f * fsig(aw[0]);

    // Peer SMEM addresses of hsm for all 4 cluster CTAs (incl. self)
    unsigned hbase = (unsigned)__cvta_generic_to_shared(hsm);
    unsigned peerh[4];
#pragma unroll
    for (int r = 0; r < 4; r++)
        asm("mapa.shared::cluster.u32 %0, %1, %2;" : "=r"(peerh[r]) : "r"(hbase), "r"(r));

    asm volatile("barrier.cluster.arrive.aligned;" ::: "memory");
    asm volatile("barrier.cluster.wait.aligned;"   ::: "memory");

    int w = tid >> 5, lane = tid & 31;
    int jsub = lane >> 3, ksub = lane & 7;
    int rbase = w*8 + jsub*2;                 // this lane's two local j rows

    // Gate-lane constants (meaningful for ksub < 4)
    int jjsel = ksub & 1, bsel = (ksub >> 1) & 1;
    int j_local = rbase + jjsel;
    int j_glob  = j0 + j_local;
    float bz = bsm[j_local], br2 = bsm[64 + j_local], bh = bsm[128 + j_local];
    const float* xz_base = &d_xzrh[((size_t)(b0 + bsel)*LL)*768 + j_glob];
    float* g_base = &d_g[((size_t)(b0 + bsel)*LL)*COUT + j_glob];

    // U row base pointers for this lane's 6 (row,gate) pairs
    const float* ubp[6];
#pragma unroll
    for (int jj = 0; jj < 2; jj++)
#pragma unroll
        for (int g = 0; g < 3; g++)
            ubp[jj*3 + g] = &Usm[g*16384 + (rbase + jj)*256];

    for (int t = 0; t < LL; t++) {
        int par = t & 1;
        const float* hin = hsm + par*512;

        // Prefetch this step's input projections (hidden by matvec)
        float xzv = 0.f, xrv = 0.f, xhv = 0.f;
        if (ksub < 4) {
            const float* p = xz_base + (size_t)t*768;
            xzv = __ldg(p); xrv = __ldg(p + 256); xhv = __ldg(p + 512);
        }

        // Load lane's strided h chunks (conflict-free: distinct ksub columns
        // within each 8-lane phase group)
        float4 hA4[8], hB4[8];
#pragma unroll
        for (int i = 0; i < 8; i++) {
            int off = (i*8 + ksub)*4;
            hA4[i] = *(const float4*)&hin[off];
            hB4[i] = *(const float4*)&hin[256 + off];
        }

        // Matvec partials: 6 (row,gate) pairs x 2 batches over 32 k-values
        float accA[6], accB[6];
#pragma unroll
        for (int pr = 0; pr < 6; pr++) {
            const float* ub = ubp[pr];
            float sA = 0.f, sB = 0.f;
#pragma unroll
            for (int i = 0; i < 8; i++) {
                float4 u4 = *(const float4*)&ub[(i*8 + ksub)*4];
                sA += u4.x*hA4[i].x + u4.y*hA4[i].y + u4.z*hA4[i].z + u4.w*hA4[i].w;
                sB += u4.x*hB4[i].x + u4.y*hB4[i].y + u4.z*hB4[i].z + u4.w*hB4[i].w;
            }
            accA[pr] = sA; accB[pr] = sB;
        }

        // 3-level butterfly over the 8 ksub lanes (all lanes end with full sums)
#pragma unroll
        for (int pr = 0; pr < 6; pr++) {
            float a = accA[pr], c = accB[pr];
            a += __shfl_xor_sync(0xffffffffu, a, 1);
            c += __shfl_xor_sync(0xffffffffu, c, 1);
            a += __shfl_xor_sync(0xffffffffu, a, 2);
            c += __shfl_xor_sync(0xffffffffu, c, 2);
            a += __shfl_xor_sync(0xffffffffu, a, 4);
            c += __shfl_xor_sync(0xffffffffu, c, 4);
            accA[pr] = a; accB[pr] = c;
        }

        // Gate update: lanes ksub<4 each handle one (jj, batch)
        if (ksub < 4) {
            float sz, sr, sh;
            if (jjsel == 0) {
                if (bsel == 0) { sz = accA[0]; sr = accA[1]; sh = accA[2]; }
                else           { sz = accB[0]; sr = accB[1]; sh = accB[2]; }
            } else {
                if (bsel == 0) { sz = accA[3]; sr = accA[4]; sh = accA[5]; }
                else           { sz = accB[3]; sr = accB[4]; sh = accB[5]; }
            }
            float z  = fsig(xzv + sz + bz);
            float r  = fsig(xrv + sr + br2);
            float hh = ftanh(xhv + r * (sh + bh));
            float hold = hin[bsel*256 + j_glob];
            float hnew = fmaf(z, hh - hold, hold);
            // Broadcast h_new into next-parity buffer of every cluster CTA
            unsigned off = (unsigned)((((par ^ 1)*512) + bsel*256 + j_glob) * 4);
#pragma unroll
            for (int rr = 0; rr < 4; rr++)
                asm volatile("st.shared::cluster.f32 [%0], %1;"
                             :: "r"(peerh[rr] + off), "f"(hnew) : "memory");
            g_base[(size_t)t*COUT] = (fabsf(hnew) < cthr) ? 0.0f : hnew;
        }

        // One cluster barrier per step (release DSMEM stores / acquire for next)
        asm volatile("barrier.cluster.arrive.aligned;" ::: "memory");
        asm volatile("barrier.cluster.wait.aligned;"   ::: "memory");
    }
}

// ---------------- Launch ----------------
extern "C" void kernel_launch(void* const* d_in, const int* in_sizes, int n_in,
                              void* d_out, int out_size)
{
    const float* x       = (const float*)d_in[0];
    const float* conv1_w = (const float*)d_in[1];
    const float* conv1_b = (const float*)d_in[2];
    const float* Wz_w = (const float*)d_in[3];  const float* Wz_b = (const float*)d_in[4];
    const float* Uz_w = (const float*)d_in[5];  const float* Uz_b = (const float*)d_in[6];
    const float* Wr_w = (const float*)d_in[7];  const float* Wr_b = (const float*)d_in[8];
    const float* Ur_w = (const float*)d_in[9];  const float* Ur_b = (const float*)d_in[10];
    const float* Wh_w = (const float*)d_in[11]; const float* Wh_b = (const float*)d_in[12];
    const float* Uh_w = (const float*)d_in[13]; const float* Uh_b = (const float*)d_in[14];
    const float* conv2_w = (const float*)d_in[15];
    const float* conv2_b = (const float*)d_in[16];
    const float* skip_w  = (const float*)d_in[17];
    const float* skip_b  = (const float*)d_in[18];
    const float* aw      = (const float*)d_in[19];
    float* out = (float*)d_out;

    prep_kernel<<<256, 256>>>(conv1_w, Wz_w, Wr_w, Wh_w, conv2_w, skip_w);
    transpose_x_kernel<<<dim3(LL/32, CIN/32, BB), dim3(32, 8)>>>(x);
    gemm_kernel<1><<<dim3(2, MROWS/128), 256>>>(conv1_b, nullptr, nullptr, nullptr);
    gemm_kernel<0><<<dim3(6, MROWS/128), 256>>>(Wz_b, Wr_b, Wh_b, nullptr);
    {
        int smem = (49152 + 1024 + 192) * (int)sizeof(float);  // 201,472 B
        cudaFuncSetAttribute(scan_kernel, cudaFuncAttributeMaxDynamicSharedMemorySize, smem);
        scan_kernel<<<128, 256, smem>>>(Uz_w, Ur_w, Uh_w, Uz_b, Ur_b, Uh_b, aw);
    }
    gemm_kernel<2><<<dim3(2, MROWS/128), 256>>>(conv2_b, nullptr, nullptr, out);
    gemm_kernel<3><<<dim3(2, MROWS/128), 256>>>(skip_b, nullptr, nullptr, out);
}

// round 14
// speedup vs baseline: 1.0036x; 1.0036x over previous
#include <cuda_runtime.h>
#include <cuda_bf16.h>
#include <cstdint>
#include <math.h>

// ---------------- Problem constants ----------------
#define BB    64
#define CIN   128
#define COUT  256
#define LL    1024
#define MROWS (BB*LL)          // 65536

// ---------------- Scratch (device globals; no allocations allowed) ----------------
__device__ float d_xT[BB*LL*CIN];          // x transposed: [b,l,i]
__device__ float d_h1t[BB*LL*COUT];        // conv1 output  [b,l,o]
__device__ float d_xzrh[BB*LL*768];        // xz|xr|xh      [b,l,768]
__device__ float d_g[BB*LL*COUT];          // gated GRU out [b,l,j]
__device__ float d_w1t[384*COUT];          // conv1 weights [tap*128+i][o]
__device__ float d_wzrh[COUT*768];         // [c][gate*256+o]
__device__ float d_w2t[768*COUT];          // conv2 weights [tap*256+j][o]
__device__ float d_swt[CIN*COUT];          // skip weights  [i][o]

// ---------------- Fast transcendentals ----------------
__device__ __forceinline__ float fexp2a(float x) {
    float y; asm("ex2.approx.f32 %0, %1;" : "=f"(y) : "f"(x)); return y;
}
__device__ __forceinline__ float frcpa(float x) {
    float y; asm("rcp.approx.f32 %0, %1;" : "=f"(y) : "f"(x)); return y;
}
__device__ __forceinline__ float fsig(float x) {        // 1/(1+e^-x)
    return frcpa(1.0f + fexp2a(-1.4426950408889634f * x));
}
__device__ __forceinline__ float ftanh(float x) {       // 2*sig(2x)-1
    return fmaf(2.0f, frcpa(1.0f + fexp2a(-2.8853900817779268f * x)), -1.0f);
}

// ---------------- Prep: weight transposes ----------------
__global__ void prep_kernel(const float* __restrict__ conv1_w,
                            const float* __restrict__ Wz, const float* __restrict__ Wr,
                            const float* __restrict__ Wh,
                            const float* __restrict__ conv2_w,
                            const float* __restrict__ skip_w)
{
    int idx = blockIdx.x * blockDim.x + threadIdx.x;
    int n = gridDim.x * blockDim.x;
    for (int t = idx; t < 384*COUT; t += n) {
        int c = t >> 8, o = t & 255;
        int tap = c / CIN, i = c % CIN;
        d_w1t[t] = conv1_w[(o*CIN + i)*3 + tap];
    }
    for (int t = idx; t < COUT*768; t += n) {
        int c = t / 768, col = t % 768;
        int gate = col >> 8, o = col & 255;
        const float* W = (gate == 0) ? Wz : (gate == 1) ? Wr : Wh;
        d_wzrh[t] = W[o*COUT + c];
    }
    for (int t = idx; t < 768*COUT; t += n) {
        int c = t >> 8, o = t & 255;
        int tap = c >> 8, j = c & 255;
        d_w2t[t] = conv2_w[(o*COUT + j)*3 + tap];
    }
    for (int t = idx; t < CIN*COUT; t += n) {
        int c = t >> 8, o = t & 255;
        d_swt[t] = skip_w[o*CIN + c];
    }
}

// ---------------- Transpose x: [B,CIN,L] -> xT [B,L,CIN] ----------------
__global__ void transpose_x_kernel(const float* __restrict__ x)
{
    __shared__ float tile[32][33];
    int b = blockIdx.z;
    int l0 = blockIdx.x * 32;
    int i0 = blockIdx.y * 32;
    int tx = threadIdx.x, ty = threadIdx.y;
    for (int r = ty; r < 32; r += 8)
        tile[r][tx] = x[(b*CIN + i0 + r)*LL + l0 + tx];
    __syncthreads();
    for (int r = ty; r < 32; r += 8)
        d_xT[(b*LL + l0 + r)*CIN + i0 + tx] = tile[tx][r];
}

// ---------------- Tiled fp32 GEMM (128x128x8, 256 threads, 8x8/thread, dbl-buf) --
template<int MODE>
__global__ __launch_bounds__(256) void gemm_kernel(const float* __restrict__ b0p,
                                                   const float* __restrict__ b1p,
                                                   const float* __restrict__ b2p,
                                                   float* __restrict__ outp)
{
    constexpr int K = (MODE == 1) ? 384 : (MODE == 0) ? 256 : (MODE == 2) ? 768 : 128;
    constexpr int N = (MODE == 0) ? 768 : 256;
    constexpr int NIT = K / 8;

    __shared__ float As[2][8][128];
    __shared__ float Bs[2][8][128];

    int tid = threadIdx.x;
    int R0 = blockIdx.y * 128;
    int n0 = blockIdx.x * 128;
    int b = R0 >> 10;
    int l0 = R0 & 1023;

    const float* Bmat = (MODE == 1) ? d_w1t : (MODE == 0) ? d_wzrh
                       : (MODE == 2) ? d_w2t : d_swt;

    int ar = tid >> 1, ac = (tid & 1) << 2;
    int br = tid >> 5, bc = (tid & 31) << 2;
    int tm4 = (tid >> 4) << 2;
    int tn4 = (tid & 15) << 2;

    float acc[8][8];
#pragma unroll
    for (int i = 0; i < 8; i++)
#pragma unroll
        for (int j = 0; j < 8; j++) acc[i][j] = 0.0f;

    auto loadA = [&](int k0) -> float4 {
        int c = k0 + ac;
        if (MODE == 0) {
            return *(const float4*)&d_h1t[(R0 + ar)*COUT + c];
        } else if (MODE == 3) {
            return *(const float4*)&d_xT[(R0 + ar)*CIN + c];
        } else if (MODE == 1) {
            int tap = c >> 7, i = c & 127;
            int lp = l0 + ar - 4 + 2*tap;
            return (lp >= 0) ? *(const float4*)&d_xT[(b*LL + lp)*CIN + i]
                             : make_float4(0.f, 0.f, 0.f, 0.f);
        } else { // MODE == 2
            int tap = c >> 8, j = c & 255;
            int lp = l0 + ar - 4 + 2*tap;
            return (lp >= 0) ? *(const float4*)&d_g[(b*LL + lp)*COUT + j]
                             : make_float4(0.f, 0.f, 0.f, 0.f);
        }
    };
    auto loadB = [&](int k0) -> float4 {
        return *(const float4*)&Bmat[(k0 + br)*N + n0 + bc];
    };

    {
        float4 av = loadA(0), bv = loadB(0);
        As[0][ac + 0][ar] = av.x; As[0][ac + 1][ar] = av.y;
        As[0][ac + 2][ar] = av.z; As[0][ac + 3][ar] = av.w;
        *(float4*)&Bs[0][br][bc] = bv;
    }
    __syncthreads();

    for (int it = 0; it < NIT; it++) {
        int buf = it & 1;
        float4 nav, nbv;
        bool have = (it + 1 < NIT);
        if (have) { nav = loadA((it + 1) * 8); nbv = loadB((it + 1) * 8); }

#pragma unroll
        for (int kk = 0; kk < 8; kk++) {
            float4 a0 = *(const float4*)&As[buf][kk][tm4];
            float4 a1 = *(const float4*)&As[buf][kk][64 + tm4];
            float4 c0 = *(const float4*)&Bs[buf][kk][tn4];
            float4 c1 = *(const float4*)&Bs[buf][kk][64 + tn4];
            float am[8] = {a0.x, a0.y, a0.z, a0.w, a1.x, a1.y, a1.z, a1.w};
            float bn[8] = {c0.x, c0.y, c0.z, c0.w, c1.x, c1.y, c1.z, c1.w};
#pragma unroll
            for (int i = 0; i < 8; i++)
#pragma unroll
                for (int j = 0; j < 8; j++) acc[i][j] += am[i] * bn[j];
        }

        if (have) {
            int nb = buf ^ 1;
            As[nb][ac + 0][ar] = nav.x; As[nb][ac + 1][ar] = nav.y;
            As[nb][ac + 2][ar] = nav.z; As[nb][ac + 3][ar] = nav.w;
            *(float4*)&Bs[nb][br][bc] = nbv;
        }
        __syncthreads();
    }

#pragma unroll
    for (int i = 0; i < 8; i++) {
        int rr = (i < 4) ? (tm4 + i) : (64 + tm4 + i - 4);
        int R = R0 + rr;
        int l = R & 1023;
#pragma unroll
        for (int j = 0; j < 8; j++) {
            int cc = (j < 4) ? (tn4 + j) : (64 + tn4 + j - 4);
            int nn = n0 + cc;
            float v = acc[i][j];
            if (MODE == 0) {
                float bias = (nn < 256) ? b0p[nn] : (nn < 512) ? b1p[nn - 256] : b2p[nn - 512];
                d_xzrh[R*768 + nn] = v + bias;
            } else if (MODE == 1) {
                v += b0p[nn];
                d_h1t[R*COUT + nn] = (v > 0.f) ? v : 0.2f * v;
            } else if (MODE == 2) {
                v += b0p[nn];
                v = (v > 0.f) ? v : 0.2f * v;
                outp[((size_t)b << 18) + ((size_t)nn << 10) + l] = v;
            } else { // MODE 3
                outp[((size_t)b << 18) + ((size_t)nn << 10) + l] += v + b0p[nn];
            }
        }
    }
}

// ---------------- Cluster-based GRU scan (8-way k-split / 4-way j-split) --------
// 32 clusters x 4 CTAs, 2 batches per cluster. CTA rank r owns j-slice
// [r*64, r*64+64) with its 192 KB U slice stationary in SMEM. Lane layout:
// jsub = lane>>3 picks a 2-row j subgroup, ksub = lane&7 picks a strided 8-way
// k-partition (chunks c == ksub mod 8). Butterfly reduction is only 3 levels
// over the 8 ksub lanes (36 shuffles vs 240 before); gate math runs straight
// from registers on lanes ksub<4 with approx sigmoid/tanh.
__global__ __launch_bounds__(256, 1) __cluster_dims__(4, 1, 1)
void scan_kernel(const float* __restrict__ Uz, const float* __restrict__ Ur,
                 const float* __restrict__ Uh,
                 const float* __restrict__ Uzb, const float* __restrict__ Urb,
                 const float* __restrict__ Uhb, const float* __restrict__ aw)
{
    extern __shared__ float sm[];
    float* Usm   = sm;             // [3][64][256] = 49152 floats (192 KB)
    float* hsm   = sm + 49152;     // [2 parities][2 batches][256]
    float* bsm   = sm + 50176;     // [3][64]

    int tid  = threadIdx.x;
    int rank = blockIdx.x & 3;
    int cid  = blockIdx.x >> 2;
    int b0 = cid * 2;
    int j0 = rank * 64;

    // Stationary U slice: Usm[g][jl][k] = Ug[(j0+jl)*256 + k]
    for (int t = tid; t < 64*256; t += 256) {
        Usm[t]         = Uz[j0*COUT + t];
        Usm[16384 + t] = Ur[j0*COUT + t];
        Usm[32768 + t] = Uh[j0*COUT + t];
    }
    if (tid < 64) {
        bsm[tid]       = Uzb[j0 + tid];
        bsm[64 + tid]  = Urb[j0 + tid];
        bsm[128 + tid] = Uhb[j0 + tid];
    }
    for (int t = tid; t < 1024; t += 256) hsm[t] = 0.f;  // h0 = 0, both parities
    float cthr = 0.1f * fsig(aw[0]);

    // Peer SMEM addresses of hsm for all 4 cluster CTAs (incl. self)
    unsigned hbase = (unsigned)__cvta_generic_to_shared(hsm);
    unsigned peerh[4];
#pragma unroll
    for (int r = 0; r < 4; r++)
        asm("mapa.shared::cluster.u32 %0, %1, %2;" : "=r"(peerh[r]) : "r"(hbase), "r"(r));

    asm volatile("barrier.cluster.arrive.aligned;" ::: "memory");
    asm volatile("barrier.cluster.wait.aligned;"   ::: "memory");

    int w = tid >> 5, lane = tid & 31;
    int jsub = lane >> 3, ksub = lane & 7;
    int rbase = w*8 + jsub*2;                 // this lane's two local j rows

    // Gate-lane constants (meaningful for ksub < 4)
    int jjsel = ksub & 1, bsel = (ksub >> 1) & 1;
    int j_local = rbase + jjsel;
    int j_glob  = j0 + j_local;
    float bz = bsm[j_local], br2 = bsm[64 + j_local], bh = bsm[128 + j_local];
    const float* xz_base = &d_xzrh[((size_t)(b0 + bsel)*LL)*768 + j_glob];
    float* g_base = &d_g[((size_t)(b0 + bsel)*LL)*COUT + j_glob];

    // U row base pointers for this lane's 6 (row,gate) pairs
    const float* ubp[6];
#pragma unroll
    for (int jj = 0; jj < 2; jj++)
#pragma unroll
        for (int g = 0; g < 3; g++)
            ubp[jj*3 + g] = &Usm[g*16384 + (rbase + jj)*256];

    for (int t = 0; t < LL; t++) {
        int par = t & 1;
        const float* hin = hsm + par*512;

        // Prefetch this step's input projections (hidden by matvec)
        float xzv = 0.f, xrv = 0.f, xhv = 0.f;
        if (ksub < 4) {
            const float* p = xz_base + (size_t)t*768;
            xzv = __ldg(p); xrv = __ldg(p + 256); xhv = __ldg(p + 512);
        }

        // Load lane's strided h chunks (conflict-free: distinct ksub columns
        // within each 8-lane phase group)
        float4 hA4[8], hB4[8];
#pragma unroll
        for (int i = 0; i < 8; i++) {
            int off = (i*8 + ksub)*4;
            hA4[i] = *(const float4*)&hin[off];
            hB4[i] = *(const float4*)&hin[256 + off];
        }

        // Matvec partials: 6 (row,gate) pairs x 2 batches over 32 k-values
        float accA[6], accB[6];
#pragma unroll
        for (int pr = 0; pr < 6; pr++) {
            const float* ub = ubp[pr];
            float sA = 0.f, sB = 0.f;
#pragma unroll
            for (int i = 0; i < 8; i++) {
                float4 u4 = *(const float4*)&ub[(i*8 + ksub)*4];
                sA += u4.x*hA4[i].x + u4.y*hA4[i].y + u4.z*hA4[i].z + u4.w*hA4[i].w;
                sB += u4.x*hB4[i].x + u4.y*hB4[i].y + u4.z*hB4[i].z + u4.w*hB4[i].w;
            }
            accA[pr] = sA; accB[pr] = sB;
        }

        // 3-level butterfly over the 8 ksub lanes (all lanes end with full sums)
#pragma unroll
        for (int pr = 0; pr < 6; pr++) {
            float a = accA[pr], c = accB[pr];
            a += __shfl_xor_sync(0xffffffffu, a, 1);
            c += __shfl_xor_sync(0xffffffffu, c, 1);
            a += __shfl_xor_sync(0xffffffffu, a, 2);
            c += __shfl_xor_sync(0xffffffffu, c, 2);
            a += __shfl_xor_sync(0xffffffffu, a, 4);
            c += __shfl_xor_sync(0xffffffffu, c, 4);
            accA[pr] = a; accB[pr] = c;
        }

        // Gate update: lanes ksub<4 each handle one (jj, batch)
        if (ksub < 4) {
            float sz, sr, sh;
            if (jjsel == 0) {
                if (bsel == 0) { sz = accA[0]; sr = accA[1]; sh = accA[2]; }
                else           { sz = accB[0]; sr = accB[1]; sh = accB[2]; }
            } else {
                if (bsel == 0) { sz = accA[3]; sr = accA[4]; sh = accA[5]; }
                else           { sz = accB[3]; sr = accB[4]; sh = accB[5]; }
            }
            float z  = fsig(xzv + sz + bz);
            float r  = fsig(xrv + sr + br2);
            float hh = ftanh(xhv + r * (sh + bh));
            float hold = hin[bsel*256 + j_glob];
            float hnew = fmaf(z, hh - hold, hold);
            // Broadcast h_new into next-parity buffer of every cluster CTA
            unsigned off = (unsigned)((((par ^ 1)*512) + bsel*256 + j_glob) * 4);
#pragma unroll
            for (int rr = 0; rr < 4; rr++)
                asm volatile("st.shared::cluster.f32 [%0], %1;"
                             :: "r"(peerh[rr] + off), "f"(hnew) : "memory");
            g_base[(size_t)t*COUT] = (fabsf(hnew) < cthr) ? 0.0f : hnew;
        }

        // One cluster barrier per step (release DSMEM stores / acquire for next)
        asm volatile("barrier.cluster.arrive.aligned;" ::: "memory");
        asm volatile("barrier.cluster.wait.aligned;"   ::: "memory");
    }
}

// ---------------- Launch ----------------
extern "C" void kernel_launch(void* const* d_in, const int* in_sizes, int n_in,
                              void* d_out, int out_size)
{
    const float* x       = (const float*)d_in[0];
    const float* conv1_w = (const float*)d_in[1];
    const float* conv1_b = (const float*)d_in[2];
    const float* Wz_w = (const float*)d_in[3];  const float* Wz_b = (const float*)d_in[4];
    const float* Uz_w = (const float*)d_in[5];  const float* Uz_b = (const float*)d_in[6];
    const float* Wr_w = (const float*)d_in[7];  const float* Wr_b = (const float*)d_in[8];
    const float* Ur_w = (const float*)d_in[9];  const float* Ur_b = (const float*)d_in[10];
    const float* Wh_w = (const float*)d_in[11]; const float* Wh_b = (const float*)d_in[12];
    const float* Uh_w = (const float*)d_in[13]; const float* Uh_b = (const float*)d_in[14];
    const float* conv2_w = (const float*)d_in[15];
    const float* conv2_b = (const float*)d_in[16];
    const float* skip_w  = (const float*)d_in[17];
    const float* skip_b  = (const float*)d_in[18];
    const float* aw      = (const float*)d_in[19];
    float* out = (float*)d_out;

    prep_kernel<<<256, 256>>>(conv1_w, Wz_w, Wr_w, Wh_w, conv2_w, skip_w);
    transpose_x_kernel<<<dim3(LL/32, CIN/32, BB), dim3(32, 8)>>>(x);
    gemm_kernel<1><<<dim3(2, MROWS/128), 256>>>(conv1_b, nullptr, nullptr, nullptr);
    gemm_kernel<0><<<dim3(6, MROWS/128), 256>>>(Wz_b, Wr_b, Wh_b, nullptr);
    {
        int smem = (49152 + 1024 + 192) * (int)sizeof(float);  // 201,472 B
        cudaFuncSetAttribute(scan_kernel, cudaFuncAttributeMaxDynamicSharedMemorySize, smem);
        scan_kernel<<<128, 256, smem>>>(Uz_w, Ur_w, Uh_w, Uz_b, Ur_b, Uh_b, aw);
    }
    gemm_kernel<2><<<dim3(2, MROWS/128), 256>>>(conv2_b, nullptr, nullptr, out);
    gemm_kernel<3><<<dim3(2, MROWS/128), 256>>>(skip_b, nullptr, nullptr, out);
}